// round 9
// baseline (speedup 1.0000x reference)
#include <cuda_runtime.h>
#include <cuda_bf16.h>
#include <cstdint>

#define B_  4
#define T_  64
#define S_  256
#define E_  512
#define D_  512
#define F_  128

#define LOG2E 1.4426950408889634f
#define SCH 8
#define TT  8

// GEMM tile config: 128x64 tile, K sliced into 128-wide slices (4 chunks of 32)
#define BM 128
#define BN 64
#define KSL 128
#define NKC 4                    // chunks per slice
#define STRIDE 36
#define STAGE_WORDS ((BM + BN) * STRIDE)
#define GEMM_SMEM_BYTES (STAGE_WORDS * 2 * 4)     // 55296 B

// -------- scratch (device globals) --------
__device__ float g_out_hs [S_ * B_ * D_];
__device__ float g_out_fds[B_ * S_ * D_];
__device__ float g_o2p    [B_ * T_ * D_];
__device__ float g_o3p    [B_ * T_ * D_];
__device__ float g_ps1    [B_ * T_ * SCH * D_];
__device__ float g_ps2    [B_ * T_ * SCH * D_];
// split-K partials (raw fp32 pre-activation)
__device__ float g_part1[4 * 1024 * 512];   // lin1: 4 slices
__device__ float g_part2[4 *  256 * 512];   // lin2: 4 slices
__device__ float g_part4[4 *  256 * 512];   // lin4: 4 slices
__device__ float g_part3[1 * 1024 * 512];   // lin3: 1 slice

struct GDesc {
    const float *A, *W;
    float* part;
    int K;        // full K of this GEMM
    int tiles;    // (M/BM) * (N/BN)
    int MN;       // M * N
    int base;     // first blockIdx
};
struct GDescs { GDesc d[4]; };

struct RDesc {
    const float* part;
    const float* bias;
    float* C;
    int MN, nsl, mode, base;
};
struct RDescs { RDesc d[4]; };

__device__ __forceinline__ uint32_t f2tf32(float x) {
    uint32_t r;
    asm("cvt.rna.tf32.f32 %0, %1;" : "=r"(r) : "f"(x));
    return r;
}
__device__ __forceinline__ uint4 cvt4(float4 v) {
    uint4 u;
    u.x = f2tf32(v.x); u.y = f2tf32(v.y); u.z = f2tf32(v.z); u.w = f2tf32(v.w);
    return u;
}
__device__ __forceinline__ uint32_t smem_u32(const void* p) {
    uint32_t a;
    asm("{ .reg .u64 t; cvta.to.shared.u64 t, %1; cvt.u32.u64 %0, t; }"
        : "=r"(a) : "l"(p));
    return a;
}

// ============================================================================
// Split-K GEMM: each block computes a 128x64 partial over one K=128 slice.
// ldmatrix + tf32 mma.sync, cvt@STS, double buffer, prefetch distance 1.
// ============================================================================
__global__ void __launch_bounds__(256)
fused_gemm_splitk(GDescs P)
{
    extern __shared__ uint32_t sm[];

    int bx = blockIdx.x;
    int gi;
    if      (bx >= P.d[3].base) gi = 3;
    else if (bx >= P.d[2].base) gi = 2;
    else if (bx >= P.d[1].base) gi = 1;
    else                        gi = 0;
    const GDesc dsc = P.d[gi];

    int local = bx - dsc.base;
    int tile  = local % dsc.tiles;
    int slice = local / dsc.tiles;
    int bm = tile >> 3;           // N/BN = 8 always (N=512)
    int bn = tile & 7;
    int m0 = bm * BM, n0 = bn * BN;
    const int K = dsc.K;

    int tid  = threadIdx.x;
    int lane = tid & 31;
    int w    = tid >> 5;
    int wm   = w & 3;
    int wn   = w >> 2;
    int fr   = lane >> 2;
    int fc   = lane & 3;

    int arow = tid >> 3;
    int acol = (tid & 7) * 4;

    int g    = lane >> 3;
    int trow = (g & 1) * 8 + (lane & 7);
    int tcol = (g >> 1) * 4;

    uint32_t sbase = smem_u32(sm);
    const uint32_t SB = STAGE_WORDS * 4u;
    uint32_t a_lm = sbase + (uint32_t)(((wm * 32 + trow) * STRIDE + tcol) * 4);
    uint32_t w_lm = sbase + (uint32_t)(((BM + wn * 32 + trow) * STRIDE + tcol) * 4);

    const float* Ag = dsc.A + (size_t)(m0 + arow) * K + slice * KSL + acol;
    const float* Wg = dsc.W + (size_t)(n0 + arow) * K + slice * KSL + acol;

    float acc[2][4][4];
#pragma unroll
    for (int a = 0; a < 2; a++)
#pragma unroll
        for (int b = 0; b < 4; b++)
#pragma unroll
            for (int c = 0; c < 4; c++) acc[a][b][c] = 0.f;

    // prologue: chunk 0 -> buffer 0
    {
        float4 t0[4], t1[2];
#pragma unroll
        for (int i = 0; i < 4; i++) t0[i] = *(const float4*)(Ag + (size_t)(32 * i) * K);
#pragma unroll
        for (int i = 0; i < 2; i++) t1[i] = *(const float4*)(Wg + (size_t)(32 * i) * K);
#pragma unroll
        for (int i = 0; i < 4; i++)
            *(uint4*)&sm[(arow + 32 * i) * STRIDE + acol] = cvt4(t0[i]);
#pragma unroll
        for (int i = 0; i < 2; i++)
            *(uint4*)&sm[(BM + arow + 32 * i) * STRIDE + acol] = cvt4(t1[i]);
    }
    __syncthreads();

#pragma unroll
    for (int ks = 0; ks < NKC; ks++) {
        int buf = ks & 1;
        bool more = (ks + 1 < NKC);

        // prefetch next chunk into registers
        float4 av[4], wv[2];
        if (more) {
            int koff = (ks + 1) << 5;
#pragma unroll
            for (int i = 0; i < 4; i++)
                av[i] = *(const float4*)(Ag + (size_t)(32 * i) * K + koff);
#pragma unroll
            for (int i = 0; i < 2; i++)
                wv[i] = *(const float4*)(Wg + (size_t)(32 * i) * K + koff);
        }

        uint32_t abase = a_lm + buf * SB;
        uint32_t wbase = w_lm + buf * SB;
#pragma unroll
        for (int kq = 0; kq < 4; kq++) {
            uint32_t a[2][4];
#pragma unroll
            for (int mf = 0; mf < 2; mf++) {
                uint32_t ad = abase + (uint32_t)((mf * 16 * STRIDE + kq * 8) * 4);
                asm volatile(
                    "ldmatrix.sync.aligned.m8n8.x4.shared.b16 {%0,%1,%2,%3}, [%4];"
                    : "=r"(a[mf][0]), "=r"(a[mf][1]), "=r"(a[mf][2]), "=r"(a[mf][3])
                    : "r"(ad));
            }
            uint32_t b[4][2];
#pragma unroll
            for (int np = 0; np < 2; np++) {
                uint32_t r0, r1, r2, r3;
                uint32_t wd = wbase + (uint32_t)((np * 16 * STRIDE + kq * 8) * 4);
                asm volatile(
                    "ldmatrix.sync.aligned.m8n8.x4.shared.b16 {%0,%1,%2,%3}, [%4];"
                    : "=r"(r0), "=r"(r1), "=r"(r2), "=r"(r3)
                    : "r"(wd));
                b[2 * np][0] = r0; b[2 * np + 1][0] = r1;
                b[2 * np][1] = r2; b[2 * np + 1][1] = r3;
            }
#pragma unroll
            for (int nf = 0; nf < 4; nf++)
#pragma unroll
                for (int mf = 0; mf < 2; mf++) {
                    asm volatile(
                        "mma.sync.aligned.m16n8k8.row.col.f32.tf32.tf32.f32 "
                        "{%0,%1,%2,%3}, {%4,%5,%6,%7}, {%8,%9}, {%0,%1,%2,%3};"
                        : "+f"(acc[mf][nf][0]), "+f"(acc[mf][nf][1]),
                          "+f"(acc[mf][nf][2]), "+f"(acc[mf][nf][3])
                        : "r"(a[mf][0]), "r"(a[mf][1]), "r"(a[mf][2]),
                          "r"(a[mf][3]), "r"(b[nf][0]), "r"(b[nf][1]));
                }
        }

        if (more) {
            uint32_t* dst = sm + (buf ^ 1) * STAGE_WORDS;
#pragma unroll
            for (int i = 0; i < 4; i++)
                *(uint4*)&dst[(arow + 32 * i) * STRIDE + acol] = cvt4(av[i]);
#pragma unroll
            for (int i = 0; i < 2; i++)
                *(uint4*)&dst[(BM + arow + 32 * i) * STRIDE + acol] = cvt4(wv[i]);
        }
        __syncthreads();
    }

    // store raw partial (no bias/activation)
    float* part = dsc.part + (size_t)slice * dsc.MN;
#pragma unroll
    for (int mf = 0; mf < 2; mf++) {
        int r0 = m0 + wm * 32 + mf * 16 + fr;
#pragma unroll
        for (int nf = 0; nf < 4; nf++) {
            int col = n0 + wn * 32 + nf * 8 + 2 * fc;
            *(float2*)&part[(size_t)r0       * 512 + col] =
                make_float2(acc[mf][nf][0], acc[mf][nf][1]);
            *(float2*)&part[(size_t)(r0 + 8) * 512 + col] =
                make_float2(acc[mf][nf][2], acc[mf][nf][3]);
        }
    }
}

// ============================================================================
// Reduce slices + bias + tanh (+ *log2e). float4 per thread.
// ============================================================================
__global__ void __launch_bounds__(256)
reduce_tanh(RDescs R)
{
    int bx = blockIdx.x;
    int gi;
    if      (bx >= R.d[3].base) gi = 3;
    else if (bx >= R.d[2].base) gi = 2;
    else if (bx >= R.d[1].base) gi = 1;
    else                        gi = 0;
    const RDesc r = R.d[gi];

    int idx = (bx - r.base) * 1024 + threadIdx.x * 4;

    float4 s = *(const float4*)&r.part[idx];
    for (int sl = 1; sl < r.nsl; sl++) {
        float4 p = *(const float4*)&r.part[(size_t)sl * r.MN + idx];
        s.x += p.x; s.y += p.y; s.z += p.z; s.w += p.w;
    }
    int col = idx & 511;
    float4 b = *(const float4*)&r.bias[col];
    float4 v;
    v.x = tanhf(s.x + b.x);
    v.y = tanhf(s.y + b.y);
    v.z = tanhf(s.z + b.z);
    v.w = tanhf(s.w + b.w);
    if (r.mode) { v.x *= LOG2E; v.y *= LOG2E; v.z *= LOG2E; v.w *= LOG2E; }
    *(float4*)&r.C[idx] = v;
}

// ============================================================================
// Attention partial over S/SCH = 32 encoder positions per block.
// ============================================================================
__global__ void __launch_bounds__(128)
dual_attn_partial(const float* __restrict__ out_hs,
                  const float* __restrict__ out_fds,
                  const float* __restrict__ enc,
                  const float* __restrict__ o2p,
                  const float* __restrict__ o3p,
                  float* __restrict__ ps1,
                  float* __restrict__ ps2)
{
    int d  = blockIdx.x * 128 + threadIdx.x;
    int t0 = blockIdx.y * TT;
    int bz = blockIdx.z;
    int b  = bz >> 3;
    int sc = bz & 7;

    float o2[TT], o3[TT], s1[TT], s2[TT];
#pragma unroll
    for (int i = 0; i < TT; i++) {
        int r = b * T_ + t0 + i;
        o2[i] = o2p[r * D_ + d];
        o3[i] = o3p[r * D_ + d];
        s1[i] = 0.f;
        s2[i] = 0.f;
    }

    const int SC = S_ / SCH;   // 32
    size_t base = ((size_t)b * S_ + sc * SC) * D_ + d;

    for (int s = 0; s < SC; s += 4) {
        float hh[4], ff[4], ee[4];
#pragma unroll
        for (int u = 0; u < 4; u++) hh[u] = out_hs [base + u * D_];
#pragma unroll
        for (int u = 0; u < 4; u++) ff[u] = out_fds[base + u * D_];
#pragma unroll
        for (int u = 0; u < 4; u++) ee[u] = enc    [base + u * D_];
        base += 4 * D_;
#pragma unroll
        for (int u = 0; u < 4; u++) {
#pragma unroll
            for (int i = 0; i < TT; i++) {
                float g = fmaf(hh[u], o2[i], ff[u] * o3[i]);
                float ex;
                asm("ex2.approx.f32 %0, %1;" : "=f"(ex) : "f"(g));
                s1[i] += ex;
                s2[i] = fmaf(ex, ee[u], s2[i]);
            }
        }
    }

#pragma unroll
    for (int i = 0; i < TT; i++) {
        size_t idx = (((size_t)(b * T_ + t0 + i)) * SCH + sc) * D_ + d;
        ps1[idx] = s1[i];
        ps2[idx] = s2[i];
    }
}

// ============================================================================
// Finalize: reduce SCH partials (float4), divide, write concat (+attn).
// ============================================================================
__global__ void __launch_bounds__(128)
attn_finalize(const float* __restrict__ ps1,
              const float* __restrict__ ps2,
              const float* __restrict__ outp,
              float* __restrict__ concat,
              float* __restrict__ attn_out)
{
    int d4 = threadIdx.x * 4;
    int r  = blockIdx.z * T_ + blockIdx.y;

    size_t base = ((size_t)r * SCH) * D_ + d4;
    float4 s1 = make_float4(0, 0, 0, 0), s2 = make_float4(0, 0, 0, 0);
#pragma unroll
    for (int sc = 0; sc < SCH; sc++) {
        float4 a = *(const float4*)&ps1[base + (size_t)sc * D_];
        float4 b = *(const float4*)&ps2[base + (size_t)sc * D_];
        s1.x += a.x; s1.y += a.y; s1.z += a.z; s1.w += a.w;
        s2.x += b.x; s2.y += b.y; s2.z += b.z; s2.w += b.w;
    }
    float4 at = make_float4(s2.x / s1.x, s2.y / s1.y, s2.z / s1.z, s2.w / s1.w);
    float4 ov = *(const float4*)&outp[(size_t)r * D_ + d4];
    *(float4*)&concat[(size_t)r * (2 * D_) + d4]      = ov;
    *(float4*)&concat[(size_t)r * (2 * D_) + D_ + d4] = at;
    if (attn_out) *(float4*)&attn_out[(size_t)r * D_ + d4] = at;
}

// ============================================================================
// kernel_launch
// ============================================================================
extern "C" void kernel_launch(void* const* d_in, const int* in_sizes, int n_in,
                              void* d_out, int out_size)
{
    const float* output = (const float*)d_in[0];
    const float* enc    = (const float*)d_in[1];
    const float* z      = (const float*)d_in[2];
    const float* W1 = (const float*)d_in[3];
    const float* b1 = (const float*)d_in[4];
    const float* W2 = (const float*)d_in[5];
    const float* b2 = (const float*)d_in[6];
    const float* W3 = (const float*)d_in[7];
    const float* b3 = (const float*)d_in[8];
    const float* W4 = (const float*)d_in[9];
    const float* b4 = (const float*)d_in[10];

    float *p_hs, *p_fds, *p_o2, *p_o3, *p_s1, *p_s2;
    float *pp1, *pp2, *pp3, *pp4;
    cudaGetSymbolAddress((void**)&p_hs,  g_out_hs);
    cudaGetSymbolAddress((void**)&p_fds, g_out_fds);
    cudaGetSymbolAddress((void**)&p_o2,  g_o2p);
    cudaGetSymbolAddress((void**)&p_o3,  g_o3p);
    cudaGetSymbolAddress((void**)&p_s1,  g_ps1);
    cudaGetSymbolAddress((void**)&p_s2,  g_ps2);
    cudaGetSymbolAddress((void**)&pp1,   g_part1);
    cudaGetSymbolAddress((void**)&pp2,   g_part2);
    cudaGetSymbolAddress((void**)&pp3,   g_part3);
    cudaGetSymbolAddress((void**)&pp4,   g_part4);

    float* concat = (float*)d_out;
    const int concat_elems = B_ * T_ * 2 * D_;
    const int attn_elems   = B_ * T_ * D_;
    float* attn_out = (out_size >= concat_elems + attn_elems)
                        ? concat + concat_elems : nullptr;

    cudaFuncSetAttribute(fused_gemm_splitk,
                         cudaFuncAttributeMaxDynamicSharedMemorySize,
                         GEMM_SMEM_BYTES);

    // split-K GEMM blocks:
    //  lin1: 64 tiles x 4 slices = 256   (base 0)
    //  lin2: 16 tiles x 4 slices = 64    (base 256)
    //  lin4: 16 tiles x 4 slices = 64    (base 320)
    //  lin3: 64 tiles x 1 slice  = 64    (base 384)   -> total 448
    GDescs G;
    G.d[0] = { enc,    W1, pp1, E_, 64, 1024 * 512,   0 };
    G.d[1] = { output, W2, pp2, D_, 16,  256 * 512, 256 };
    G.d[2] = { output, W4, pp4, D_, 16,  256 * 512, 320 };
    G.d[3] = { z,      W3, pp3, F_, 64, 1024 * 512, 384 };

    fused_gemm_splitk<<<448, 256, GEMM_SMEM_BYTES>>>(G);

    // reduce blocks: lin1 512, lin2 128, lin4 128, lin3 512 -> 1280
    RDescs R;
    R.d[0] = { pp1, b1, p_hs,  1024 * 512, 4, 0,    0 };
    R.d[1] = { pp2, b2, p_o2,   256 * 512, 4, 1,  512 };
    R.d[2] = { pp4, b4, p_o3,   256 * 512, 4, 1,  640 };
    R.d[3] = { pp3, b3, p_fds, 1024 * 512, 1, 0,  768 };

    reduce_tanh<<<1280, 256>>>(R);

    dual_attn_partial<<<dim3(D_ / 128, T_ / TT, B_ * SCH), 128>>>(
        p_hs, p_fds, enc, p_o2, p_o3, p_s1, p_s2);

    attn_finalize<<<dim3(1, T_, B_), 128>>>(
        p_s1, p_s2, output, concat, attn_out);
}

// round 10
// speedup vs baseline: 1.0823x; 1.0823x over previous
#include <cuda_runtime.h>
#include <cuda_bf16.h>
#include <cstdint>

#define B_  4
#define T_  64
#define S_  256
#define E_  512
#define D_  512
#define F_  128

#define LOG2E 1.4426950408889634f
#define SCH 8
#define TT  8

// GEMM tile config: 64x64 block, 4 warps (2m x 2n), K chunks of 32, 4-stage cp.async
#define BM 64
#define BN 64
#define STRIDE 36
#define STG_WORDS ((BM + BN) * STRIDE)            // 4608 words = 18432 B
#define NSTG 4
#define GEMM_SMEM_BYTES (STG_WORDS * NSTG * 4)    // 73728 B

// -------- scratch (device globals) --------
__device__ float g_out_hs [S_ * B_ * D_];
__device__ float g_out_fds[B_ * S_ * D_];
__device__ float g_o2p    [B_ * T_ * D_];
__device__ float g_o3p    [B_ * T_ * D_];
__device__ float g_ps1    [B_ * T_ * SCH * D_];
__device__ float g_ps2    [B_ * T_ * SCH * D_];
// tf32-pre-rounded copies of GEMM inputs (so mainloop needs NO cvt)
__device__ float g_enc_r[S_ * B_ * E_];
__device__ float g_out_r[B_ * T_ * D_];
__device__ float g_z_r  [B_ * S_ * F_];
__device__ float g_W1r[D_ * E_];
__device__ float g_W2r[D_ * D_];
__device__ float g_W3r[D_ * F_];
__device__ float g_W4r[D_ * D_];

__device__ __forceinline__ float f2tf32f(float x) {
    uint32_t r;
    asm("cvt.rna.tf32.f32 %0, %1;" : "=r"(r) : "f"(x));
    return __uint_as_float(r);
}
__device__ __forceinline__ uint32_t smem_u32(const void* p) {
    uint32_t a;
    asm("{ .reg .u64 t; cvta.to.shared.u64 t, %1; cvt.u32.u64 %0, t; }"
        : "=r"(a) : "l"(p));
    return a;
}
__device__ __forceinline__ void cp16(uint32_t dst, const void* src) {
    asm volatile("cp.async.cg.shared.global [%0], [%1], 16;"
                 :: "r"(dst), "l"(src));
}

// ============================================================================
// Pre-round: tf32(rna) copies of the 7 GEMM input tensors. float4 per thread.
// ============================================================================
struct PRD { const float* s; float* d; int base; };
struct PRDs { PRD p[7]; };

__global__ void __launch_bounds__(256)
preround_tf32(PRDs P)
{
    int bx = blockIdx.x;
    int gi = 0;
#pragma unroll
    for (int i = 1; i < 7; i++) if (bx >= P.p[i].base) gi = i;
    const PRD pr = P.p[gi];
    int idx = (bx - pr.base) * 1024 + threadIdx.x * 4;
    float4 v = *(const float4*)&pr.s[idx];
    float4 o;
    o.x = f2tf32f(v.x); o.y = f2tf32f(v.y);
    o.z = f2tf32f(v.z); o.w = f2tf32f(v.w);
    *(float4*)&pr.d[idx] = o;
}

// ============================================================================
// Fused 4-in-1 GEMM on pre-rounded inputs: cp.async(4-stage) -> ldmatrix ->
// mma.tf32. 64x64 block, 128 threads, 4 warps (2m x 2n), 32x32 warp tiles.
// C = tanh(A @ W^T + bias) [* log2e]
// ============================================================================
struct Desc {
    const float *A, *W, *bias;
    float *C;
    int K, mode, base, bncnt;
};
struct Descs { Desc d[4]; };

__global__ void __launch_bounds__(128)
fused_gemm_tf32(Descs P)
{
    extern __shared__ uint32_t sm[];

    int bx = blockIdx.x;
    int gi;
    if      (bx >= P.d[3].base) gi = 3;
    else if (bx >= P.d[2].base) gi = 2;
    else if (bx >= P.d[1].base) gi = 1;
    else                        gi = 0;
    const Desc dsc = P.d[gi];

    int local = bx - dsc.base;
    int bm = local / dsc.bncnt;
    int bn = local - bm * dsc.bncnt;
    int m0 = bm * BM, n0 = bn * BN;
    const int K = dsc.K;
    const int nk = K >> 5;      // >= 4 for all four GEMMs

    int tid  = threadIdx.x;
    int lane = tid & 31;
    int w    = tid >> 5;
    int wm   = w & 1;
    int wn   = w >> 1;
    int fr   = lane >> 2;
    int fc   = lane & 3;

    // cp.async mapping: 2 threads per 32-word row; 4 x 16B each
    int arow = tid >> 1;              // 0..63
    int colb = (tid & 1) * 16;        // word 0 or 16

    // ldmatrix lane mapping
    int g    = lane >> 3;
    int trow = (g & 1) * 8 + (lane & 7);
    int tcol = (g >> 1) * 4;

    uint32_t sbase = smem_u32(sm);
    const uint32_t SB = STG_WORDS * 4u;
    uint32_t a_lm = sbase + (uint32_t)(((wm * 32 + trow) * STRIDE + tcol) * 4);
    uint32_t w_lm = sbase + (uint32_t)(((BM + wn * 32 + trow) * STRIDE + tcol) * 4);

    const float* Ag = dsc.A + (size_t)(m0 + arow) * K + colb;
    const float* Wg = dsc.W + (size_t)(n0 + arow) * K + colb;

    // issue one stage: 64x32 of A + 64x32 of W
    auto issue = [&](int ks, int stg) {
        uint32_t sb = sbase + (uint32_t)stg * SB;
        int koff = ks << 5;
        uint32_t da = sb + (uint32_t)((arow * STRIDE + colb) * 4);
        uint32_t dw = sb + (uint32_t)(((BM + arow) * STRIDE + colb) * 4);
        const float* sa = Ag + koff;
        const float* sw = Wg + koff;
#pragma unroll
        for (int j = 0; j < 4; j++) cp16(da + j * 16, sa + j * 4);
#pragma unroll
        for (int j = 0; j < 4; j++) cp16(dw + j * 16, sw + j * 4);
        asm volatile("cp.async.commit_group;" ::: "memory");
    };

    float acc[2][4][4];
#pragma unroll
    for (int a = 0; a < 2; a++)
#pragma unroll
        for (int b = 0; b < 4; b++)
#pragma unroll
            for (int c = 0; c < 4; c++) acc[a][b][c] = 0.f;

    issue(0, 0);
    issue(1, 1);
    issue(2, 2);

    for (int ks = 0; ks < nk; ks++) {
        // chunk ks is in group #ks; allow min(2, nk-1-ks) groups pending
        int pend = nk - 1 - ks;
        if (pend >= 2)      asm volatile("cp.async.wait_group 2;" ::: "memory");
        else if (pend == 1) asm volatile("cp.async.wait_group 1;" ::: "memory");
        else                asm volatile("cp.async.wait_group 0;" ::: "memory");
        __syncthreads();

        if (ks + 3 < nk) issue(ks + 3, (ks + 3) & 3);

        uint32_t abase = a_lm + (uint32_t)(ks & 3) * SB;
        uint32_t wbase = w_lm + (uint32_t)(ks & 3) * SB;
#pragma unroll
        for (int kq = 0; kq < 4; kq++) {
            uint32_t a[2][4];
#pragma unroll
            for (int mf = 0; mf < 2; mf++) {
                uint32_t ad = abase + (uint32_t)((mf * 16 * STRIDE + kq * 8) * 4);
                asm volatile(
                    "ldmatrix.sync.aligned.m8n8.x4.shared.b16 {%0,%1,%2,%3}, [%4];"
                    : "=r"(a[mf][0]), "=r"(a[mf][1]), "=r"(a[mf][2]), "=r"(a[mf][3])
                    : "r"(ad));
            }
            uint32_t b[4][2];
#pragma unroll
            for (int np = 0; np < 2; np++) {
                uint32_t r0, r1, r2, r3;
                uint32_t wd = wbase + (uint32_t)((np * 16 * STRIDE + kq * 8) * 4);
                asm volatile(
                    "ldmatrix.sync.aligned.m8n8.x4.shared.b16 {%0,%1,%2,%3}, [%4];"
                    : "=r"(r0), "=r"(r1), "=r"(r2), "=r"(r3)
                    : "r"(wd));
                b[2 * np][0] = r0; b[2 * np + 1][0] = r1;
                b[2 * np][1] = r2; b[2 * np + 1][1] = r3;
            }
#pragma unroll
            for (int nf = 0; nf < 4; nf++)
#pragma unroll
                for (int mf = 0; mf < 2; mf++) {
                    asm volatile(
                        "mma.sync.aligned.m16n8k8.row.col.f32.tf32.tf32.f32 "
                        "{%0,%1,%2,%3}, {%4,%5,%6,%7}, {%8,%9}, {%0,%1,%2,%3};"
                        : "+f"(acc[mf][nf][0]), "+f"(acc[mf][nf][1]),
                          "+f"(acc[mf][nf][2]), "+f"(acc[mf][nf][3])
                        : "r"(a[mf][0]), "r"(a[mf][1]), "r"(a[mf][2]),
                          "r"(a[mf][3]), "r"(b[nf][0]), "r"(b[nf][1]));
                }
        }
    }

    // epilogue: bias + tanh (+ *log2e)
#pragma unroll
    for (int mf = 0; mf < 2; mf++) {
        int r0 = m0 + wm * 32 + mf * 16 + fr;
#pragma unroll
        for (int nf = 0; nf < 4; nf++) {
            int col = n0 + wn * 32 + nf * 8 + 2 * fc;
            float bb0 = dsc.bias[col];
            float bb1 = dsc.bias[col + 1];
            float v0 = tanhf(acc[mf][nf][0] + bb0);
            float v1 = tanhf(acc[mf][nf][1] + bb1);
            float v2 = tanhf(acc[mf][nf][2] + bb0);
            float v3 = tanhf(acc[mf][nf][3] + bb1);
            if (dsc.mode) { v0 *= LOG2E; v1 *= LOG2E; v2 *= LOG2E; v3 *= LOG2E; }
            *(float2*)&dsc.C[(size_t)r0       * D_ + col] = make_float2(v0, v1);
            *(float2*)&dsc.C[(size_t)(r0 + 8) * D_ + col] = make_float2(v2, v3);
        }
    }
}

// ============================================================================
// Attention partial over S/SCH = 32 encoder positions per block.
// ============================================================================
__global__ void __launch_bounds__(128)
dual_attn_partial(const float* __restrict__ out_hs,
                  const float* __restrict__ out_fds,
                  const float* __restrict__ enc,
                  const float* __restrict__ o2p,
                  const float* __restrict__ o3p,
                  float* __restrict__ ps1,
                  float* __restrict__ ps2)
{
    int d  = blockIdx.x * 128 + threadIdx.x;
    int t0 = blockIdx.y * TT;
    int bz = blockIdx.z;
    int b  = bz >> 3;
    int sc = bz & 7;

    float o2[TT], o3[TT], s1[TT], s2[TT];
#pragma unroll
    for (int i = 0; i < TT; i++) {
        int r = b * T_ + t0 + i;
        o2[i] = o2p[r * D_ + d];
        o3[i] = o3p[r * D_ + d];
        s1[i] = 0.f;
        s2[i] = 0.f;
    }

    const int SC = S_ / SCH;   // 32
    size_t base = ((size_t)b * S_ + sc * SC) * D_ + d;

    for (int s = 0; s < SC; s += 4) {
        float hh[4], ff[4], ee[4];
#pragma unroll
        for (int u = 0; u < 4; u++) hh[u] = out_hs [base + u * D_];
#pragma unroll
        for (int u = 0; u < 4; u++) ff[u] = out_fds[base + u * D_];
#pragma unroll
        for (int u = 0; u < 4; u++) ee[u] = enc    [base + u * D_];
        base += 4 * D_;
#pragma unroll
        for (int u = 0; u < 4; u++) {
#pragma unroll
            for (int i = 0; i < TT; i++) {
                float g = fmaf(hh[u], o2[i], ff[u] * o3[i]);
                float ex;
                asm("ex2.approx.f32 %0, %1;" : "=f"(ex) : "f"(g));
                s1[i] += ex;
                s2[i] = fmaf(ex, ee[u], s2[i]);
            }
        }
    }

#pragma unroll
    for (int i = 0; i < TT; i++) {
        size_t idx = (((size_t)(b * T_ + t0 + i)) * SCH + sc) * D_ + d;
        ps1[idx] = s1[i];
        ps2[idx] = s2[i];
    }
}

// ============================================================================
// Finalize: reduce SCH partials, divide, write concat (+attn).
// Grid (2, T_, B_) = 512 blocks, 128 threads, 2 d's per thread (float2).
// ============================================================================
__global__ void __launch_bounds__(128)
attn_finalize(const float* __restrict__ ps1,
              const float* __restrict__ ps2,
              const float* __restrict__ outp,
              float* __restrict__ concat,
              float* __restrict__ attn_out)
{
    int d2 = blockIdx.x * 256 + threadIdx.x * 2;
    int r  = blockIdx.z * T_ + blockIdx.y;

    size_t base = ((size_t)r * SCH) * D_ + d2;
    float2 s1 = make_float2(0, 0), s2 = make_float2(0, 0);
#pragma unroll
    for (int sc = 0; sc < SCH; sc++) {
        float2 a = *(const float2*)&ps1[base + (size_t)sc * D_];
        float2 b = *(const float2*)&ps2[base + (size_t)sc * D_];
        s1.x += a.x; s1.y += a.y;
        s2.x += b.x; s2.y += b.y;
    }
    float2 at = make_float2(s2.x / s1.x, s2.y / s1.y);
    float2 ov = *(const float2*)&outp[(size_t)r * D_ + d2];
    *(float2*)&concat[(size_t)r * (2 * D_) + d2]      = ov;
    *(float2*)&concat[(size_t)r * (2 * D_) + D_ + d2] = at;
    if (attn_out) *(float2*)&attn_out[(size_t)r * D_ + d2] = at;
}

// ============================================================================
// kernel_launch
// ============================================================================
extern "C" void kernel_launch(void* const* d_in, const int* in_sizes, int n_in,
                              void* d_out, int out_size)
{
    const float* output = (const float*)d_in[0];
    const float* enc    = (const float*)d_in[1];
    const float* z      = (const float*)d_in[2];
    const float* W1 = (const float*)d_in[3];
    const float* b1 = (const float*)d_in[4];
    const float* W2 = (const float*)d_in[5];
    const float* b2 = (const float*)d_in[6];
    const float* W3 = (const float*)d_in[7];
    const float* b3 = (const float*)d_in[8];
    const float* W4 = (const float*)d_in[9];
    const float* b4 = (const float*)d_in[10];

    float *p_hs, *p_fds, *p_o2, *p_o3, *p_s1, *p_s2;
    float *r_enc, *r_out, *r_z, *r_W1, *r_W2, *r_W3, *r_W4;
    cudaGetSymbolAddress((void**)&p_hs,  g_out_hs);
    cudaGetSymbolAddress((void**)&p_fds, g_out_fds);
    cudaGetSymbolAddress((void**)&p_o2,  g_o2p);
    cudaGetSymbolAddress((void**)&p_o3,  g_o3p);
    cudaGetSymbolAddress((void**)&p_s1,  g_ps1);
    cudaGetSymbolAddress((void**)&p_s2,  g_ps2);
    cudaGetSymbolAddress((void**)&r_enc, g_enc_r);
    cudaGetSymbolAddress((void**)&r_out, g_out_r);
    cudaGetSymbolAddress((void**)&r_z,   g_z_r);
    cudaGetSymbolAddress((void**)&r_W1,  g_W1r);
    cudaGetSymbolAddress((void**)&r_W2,  g_W2r);
    cudaGetSymbolAddress((void**)&r_W3,  g_W3r);
    cudaGetSymbolAddress((void**)&r_W4,  g_W4r);

    float* concat = (float*)d_out;
    const int concat_elems = B_ * T_ * 2 * D_;
    const int attn_elems   = B_ * T_ * D_;
    float* attn_out = (out_size >= concat_elems + attn_elems)
                        ? concat + concat_elems : nullptr;

    cudaFuncSetAttribute(fused_gemm_tf32,
                         cudaFuncAttributeMaxDynamicSharedMemorySize,
                         GEMM_SMEM_BYTES);

    // Pre-round all GEMM inputs to tf32 (rna). Block = 1024 floats.
    // sizes/1024: enc 512, out 128, z 128, W1 256, W2 256, W3 64, W4 256 -> 1600
    PRDs PR;
    PR.p[0] = { enc,    r_enc,    0 };
    PR.p[1] = { output, r_out,  512 };
    PR.p[2] = { z,      r_z,    640 };
    PR.p[3] = { W1,     r_W1,   768 };
    PR.p[4] = { W2,     r_W2,  1024 };
    PR.p[5] = { W3,     r_W3,  1280 };
    PR.p[6] = { W4,     r_W4,  1344 };
    preround_tf32<<<1600, 256>>>(PR);

    // GEMM blocks (heavy first, light lin3 last):
    //  lin1: 16m x 8n = 128  (base 0)
    //  lin2:  4m x 8n =  32  (base 128)
    //  lin4:  4m x 8n =  32  (base 160)
    //  lin3: 16m x 8n = 128  (base 192)   -> 320 total
    Descs P;
    P.d[0] = { r_enc, r_W1, b1, p_hs,  E_, 0,   0, D_ / BN };
    P.d[1] = { r_out, r_W2, b2, p_o2,  D_, 1, 128, D_ / BN };
    P.d[2] = { r_out, r_W4, b4, p_o3,  D_, 1, 160, D_ / BN };
    P.d[3] = { r_z,   r_W3, b3, p_fds, F_, 0, 192, D_ / BN };

    fused_gemm_tf32<<<320, 128, GEMM_SMEM_BYTES>>>(P);

    dual_attn_partial<<<dim3(D_ / 128, T_ / TT, B_ * SCH), 128>>>(
        p_hs, p_fds, enc, p_o2, p_o3, p_s1, p_s2);

    attn_finalize<<<dim3(2, T_, B_), 128>>>(
        p_s1, p_s2, output, concat, attn_out);
}

// round 11
// speedup vs baseline: 1.1975x; 1.1065x over previous
#include <cuda_runtime.h>
#include <cuda_bf16.h>
#include <cstdint>

#define B_  4
#define T_  64
#define S_  256
#define E_  512
#define D_  512
#define F_  128

#define LOG2E 1.4426950408889634f
#define SCH 8
#define TT  8

// GEMM: 64x64 block, 256 threads, 8 warps (2m x 4n, warp tile 32x16),
// K chunks of 32, 4-stage cp.async ring.
#define BM 64
#define BN 64
#define STRIDE 36
#define STG_WORDS ((BM + BN) * STRIDE)            // 4608 words = 18432 B
#define NSTG 4
#define GEMM_SMEM_BYTES (STG_WORDS * NSTG * 4)    // 73728 B

// -------- scratch (device globals) --------
__device__ float g_out_hs [S_ * B_ * D_];
__device__ float g_out_fds[B_ * S_ * D_];
__device__ float g_o2p    [B_ * T_ * D_];
__device__ float g_o3p    [B_ * T_ * D_];
__device__ float g_ps1    [B_ * T_ * SCH * D_];
__device__ float g_ps2    [B_ * T_ * SCH * D_];
// tf32-pre-rounded copies of GEMM inputs (mainloop has NO cvt)
__device__ float g_enc_r[S_ * B_ * E_];
__device__ float g_out_r[B_ * T_ * D_];
__device__ float g_z_r  [B_ * S_ * F_];
__device__ float g_W1r[D_ * E_];
__device__ float g_W2r[D_ * D_];
__device__ float g_W3r[D_ * F_];
__device__ float g_W4r[D_ * D_];

__device__ __forceinline__ float f2tf32f(float x) {
    uint32_t r;
    asm("cvt.rna.tf32.f32 %0, %1;" : "=r"(r) : "f"(x));
    return __uint_as_float(r);
}
__device__ __forceinline__ uint32_t smem_u32(const void* p) {
    uint32_t a;
    asm("{ .reg .u64 t; cvta.to.shared.u64 t, %1; cvt.u32.u64 %0, t; }"
        : "=r"(a) : "l"(p));
    return a;
}
__device__ __forceinline__ void cp16(uint32_t dst, const void* src) {
    asm volatile("cp.async.cg.shared.global [%0], [%1], 16;"
                 :: "r"(dst), "l"(src));
}

// ============================================================================
// Pre-round: tf32(rna) copies of the 7 GEMM input tensors. float4 per thread.
// ============================================================================
struct PRD { const float* s; float* d; int base; };
struct PRDs { PRD p[7]; };

__global__ void __launch_bounds__(256)
preround_tf32(PRDs P)
{
    int bx = blockIdx.x;
    int gi = 0;
#pragma unroll
    for (int i = 1; i < 7; i++) if (bx >= P.p[i].base) gi = i;
    const PRD pr = P.p[gi];
    int idx = (bx - pr.base) * 1024 + threadIdx.x * 4;
    float4 v = *(const float4*)&pr.s[idx];
    float4 o;
    o.x = f2tf32f(v.x); o.y = f2tf32f(v.y);
    o.z = f2tf32f(v.z); o.w = f2tf32f(v.w);
    *(float4*)&pr.d[idx] = o;
}

// ============================================================================
// Fused 4-in-1 GEMM on pre-rounded inputs.
// C = tanh(A @ W^T + bias) [* log2e]
// ============================================================================
struct Desc {
    const float *A, *W, *bias;
    float *C;
    int K, mode, base, bncnt;
};
struct Descs { Desc d[4]; };

__global__ void __launch_bounds__(256)
fused_gemm_tf32(Descs P)
{
    extern __shared__ uint32_t sm[];

    int bx = blockIdx.x;
    int gi;
    if      (bx >= P.d[3].base) gi = 3;
    else if (bx >= P.d[2].base) gi = 2;
    else if (bx >= P.d[1].base) gi = 1;
    else                        gi = 0;
    const Desc dsc = P.d[gi];

    int local = bx - dsc.base;
    int bm = local / dsc.bncnt;
    int bn = local - bm * dsc.bncnt;
    int m0 = bm * BM, n0 = bn * BN;
    const int K = dsc.K;
    const int nk = K >> 5;          // 4 or 16

    int tid  = threadIdx.x;
    int lane = tid & 31;
    int w    = tid >> 5;
    int wm   = w & 1;               // m group (32 rows)
    int wn   = w >> 1;              // n group (16 cols), 0..3
    int fr   = lane >> 2;
    int fc   = lane & 3;

    // cp.async mapping: 4 threads per 32-word row, 2x16B each
    int arow  = tid >> 2;           // 0..63
    int acolw = (tid & 3) * 8;      // word col 0,8,16,24

    // ldmatrix lane->tile-row mapping
    int g    = lane >> 3;
    int trow = (g & 1) * 8 + (lane & 7);   // 0..15
    int tcol = (g >> 1) * 4;               // 0 or 4

    uint32_t sbase = smem_u32(sm);
    const uint32_t SB = STG_WORDS * 4u;
    uint32_t a_lm = sbase + (uint32_t)(((wm * 32 + trow) * STRIDE + tcol) * 4);
    uint32_t w_lm = sbase + (uint32_t)(((BM + wn * 16 + trow) * STRIDE + tcol) * 4);

    const float* Ag = dsc.A + (size_t)(m0 + arow) * K + acolw;
    const float* Wg = dsc.W + (size_t)(n0 + arow) * K + acolw;

    auto issue = [&](int ks, int stg) {
        uint32_t sb = sbase + (uint32_t)stg * SB;
        int koff = ks << 5;
        uint32_t da = sb + (uint32_t)((arow * STRIDE + acolw) * 4);
        uint32_t dw = sb + (uint32_t)(((BM + arow) * STRIDE + acolw) * 4);
        const float* sa = Ag + koff;
        const float* sw = Wg + koff;
        cp16(da,      sa);
        cp16(da + 16, sa + 4);
        cp16(dw,      sw);
        cp16(dw + 16, sw + 4);
        asm volatile("cp.async.commit_group;" ::: "memory");
    };

    float acc[2][2][4];
#pragma unroll
    for (int a = 0; a < 2; a++)
#pragma unroll
        for (int b = 0; b < 2; b++)
#pragma unroll
            for (int c = 0; c < 4; c++) acc[a][b][c] = 0.f;

    issue(0, 0);
    issue(1, 1);
    issue(2, 2);

    for (int ks = 0; ks < nk; ks++) {
        int pend = nk - 1 - ks;
        if (pend >= 2)      asm volatile("cp.async.wait_group 2;" ::: "memory");
        else if (pend == 1) asm volatile("cp.async.wait_group 1;" ::: "memory");
        else                asm volatile("cp.async.wait_group 0;" ::: "memory");
        __syncthreads();

        if (ks + 3 < nk) issue(ks + 3, (ks + 3) & 3);

        uint32_t abase = a_lm + (uint32_t)(ks & 3) * SB;
        uint32_t wbase = w_lm + (uint32_t)(ks & 3) * SB;
#pragma unroll
        for (int kq = 0; kq < 4; kq++) {
            // A: two m16k8 frags (32 rows)
            uint32_t a[2][4];
#pragma unroll
            for (int mf = 0; mf < 2; mf++) {
                uint32_t ad = abase + (uint32_t)((mf * 16 * STRIDE + kq * 8) * 4);
                asm volatile(
                    "ldmatrix.sync.aligned.m8n8.x4.shared.b16 {%0,%1,%2,%3}, [%4];"
                    : "=r"(a[mf][0]), "=r"(a[mf][1]), "=r"(a[mf][2]), "=r"(a[mf][3])
                    : "r"(ad));
            }
            // B: one x4 covers 16 cols x 8k -> two n8 frags
            uint32_t r0, r1, r2, r3;
            uint32_t wd = wbase + (uint32_t)((kq * 8) * 4);
            asm volatile(
                "ldmatrix.sync.aligned.m8n8.x4.shared.b16 {%0,%1,%2,%3}, [%4];"
                : "=r"(r0), "=r"(r1), "=r"(r2), "=r"(r3)
                : "r"(wd));
            uint32_t b[2][2];
            b[0][0] = r0; b[0][1] = r2;    // cols 0-7
            b[1][0] = r1; b[1][1] = r3;    // cols 8-15
#pragma unroll
            for (int nf = 0; nf < 2; nf++)
#pragma unroll
                for (int mf = 0; mf < 2; mf++) {
                    asm volatile(
                        "mma.sync.aligned.m16n8k8.row.col.f32.tf32.tf32.f32 "
                        "{%0,%1,%2,%3}, {%4,%5,%6,%7}, {%8,%9}, {%0,%1,%2,%3};"
                        : "+f"(acc[mf][nf][0]), "+f"(acc[mf][nf][1]),
                          "+f"(acc[mf][nf][2]), "+f"(acc[mf][nf][3])
                        : "r"(a[mf][0]), "r"(a[mf][1]), "r"(a[mf][2]),
                          "r"(a[mf][3]), "r"(b[nf][0]), "r"(b[nf][1]));
                }
        }
    }

    // epilogue: bias + tanh (+ *log2e)
#pragma unroll
    for (int mf = 0; mf < 2; mf++) {
        int r0 = m0 + wm * 32 + mf * 16 + fr;
#pragma unroll
        for (int nf = 0; nf < 2; nf++) {
            int col = n0 + wn * 16 + nf * 8 + 2 * fc;
            float bb0 = dsc.bias[col];
            float bb1 = dsc.bias[col + 1];
            float v0 = tanhf(acc[mf][nf][0] + bb0);
            float v1 = tanhf(acc[mf][nf][1] + bb1);
            float v2 = tanhf(acc[mf][nf][2] + bb0);
            float v3 = tanhf(acc[mf][nf][3] + bb1);
            if (dsc.mode) { v0 *= LOG2E; v1 *= LOG2E; v2 *= LOG2E; v3 *= LOG2E; }
            *(float2*)&dsc.C[(size_t)r0       * D_ + col] = make_float2(v0, v1);
            *(float2*)&dsc.C[(size_t)(r0 + 8) * D_ + col] = make_float2(v2, v3);
        }
    }
}

// ============================================================================
// Attention partial over S/SCH = 32 encoder positions per block.
// ============================================================================
__global__ void __launch_bounds__(128)
dual_attn_partial(const float* __restrict__ out_hs,
                  const float* __restrict__ out_fds,
                  const float* __restrict__ enc,
                  const float* __restrict__ o2p,
                  const float* __restrict__ o3p,
                  float* __restrict__ ps1,
                  float* __restrict__ ps2)
{
    int d  = blockIdx.x * 128 + threadIdx.x;
    int t0 = blockIdx.y * TT;
    int bz = blockIdx.z;
    int b  = bz >> 3;
    int sc = bz & 7;

    float o2[TT], o3[TT], s1[TT], s2[TT];
#pragma unroll
    for (int i = 0; i < TT; i++) {
        int r = b * T_ + t0 + i;
        o2[i] = o2p[r * D_ + d];
        o3[i] = o3p[r * D_ + d];
        s1[i] = 0.f;
        s2[i] = 0.f;
    }

    const int SC = S_ / SCH;   // 32
    size_t base = ((size_t)b * S_ + sc * SC) * D_ + d;

    for (int s = 0; s < SC; s += 4) {
        float hh[4], ff[4], ee[4];
#pragma unroll
        for (int u = 0; u < 4; u++) hh[u] = out_hs [base + u * D_];
#pragma unroll
        for (int u = 0; u < 4; u++) ff[u] = out_fds[base + u * D_];
#pragma unroll
        for (int u = 0; u < 4; u++) ee[u] = enc    [base + u * D_];
        base += 4 * D_;
#pragma unroll
        for (int u = 0; u < 4; u++) {
#pragma unroll
            for (int i = 0; i < TT; i++) {
                float g = fmaf(hh[u], o2[i], ff[u] * o3[i]);
                float ex;
                asm("ex2.approx.f32 %0, %1;" : "=f"(ex) : "f"(g));
                s1[i] += ex;
                s2[i] = fmaf(ex, ee[u], s2[i]);
            }
        }
    }

#pragma unroll
    for (int i = 0; i < TT; i++) {
        size_t idx = (((size_t)(b * T_ + t0 + i)) * SCH + sc) * D_ + d;
        ps1[idx] = s1[i];
        ps2[idx] = s2[i];
    }
}

// ============================================================================
// Finalize: reduce SCH partials, divide, write concat (+attn).
// Grid (4, T_, B_) = 1024 blocks, 128 threads, 1 d per thread.
// ============================================================================
__global__ void __launch_bounds__(128)
attn_finalize(const float* __restrict__ ps1,
              const float* __restrict__ ps2,
              const float* __restrict__ outp,
              float* __restrict__ concat,
              float* __restrict__ attn_out)
{
    int d = blockIdx.x * 128 + threadIdx.x;
    int r = blockIdx.z * T_ + blockIdx.y;

    size_t base = ((size_t)r * SCH) * D_ + d;
    float a0 = 0.f, a1 = 0.f;
#pragma unroll
    for (int sc = 0; sc < SCH; sc++) {
        a0 += ps1[base + (size_t)sc * D_];
        a1 += ps2[base + (size_t)sc * D_];
    }
    float at = a1 / a0;
    concat[(size_t)r * (2 * D_) + d]      = outp[(size_t)r * D_ + d];
    concat[(size_t)r * (2 * D_) + D_ + d] = at;
    if (attn_out) attn_out[(size_t)r * D_ + d] = at;
}

// ============================================================================
// kernel_launch
// ============================================================================
extern "C" void kernel_launch(void* const* d_in, const int* in_sizes, int n_in,
                              void* d_out, int out_size)
{
    const float* output = (const float*)d_in[0];
    const float* enc    = (const float*)d_in[1];
    const float* z      = (const float*)d_in[2];
    const float* W1 = (const float*)d_in[3];
    const float* b1 = (const float*)d_in[4];
    const float* W2 = (const float*)d_in[5];
    const float* b2 = (const float*)d_in[6];
    const float* W3 = (const float*)d_in[7];
    const float* b3 = (const float*)d_in[8];
    const float* W4 = (const float*)d_in[9];
    const float* b4 = (const float*)d_in[10];

    float *p_hs, *p_fds, *p_o2, *p_o3, *p_s1, *p_s2;
    float *r_enc, *r_out, *r_z, *r_W1, *r_W2, *r_W3, *r_W4;
    cudaGetSymbolAddress((void**)&p_hs,  g_out_hs);
    cudaGetSymbolAddress((void**)&p_fds, g_out_fds);
    cudaGetSymbolAddress((void**)&p_o2,  g_o2p);
    cudaGetSymbolAddress((void**)&p_o3,  g_o3p);
    cudaGetSymbolAddress((void**)&p_s1,  g_ps1);
    cudaGetSymbolAddress((void**)&p_s2,  g_ps2);
    cudaGetSymbolAddress((void**)&r_enc, g_enc_r);
    cudaGetSymbolAddress((void**)&r_out, g_out_r);
    cudaGetSymbolAddress((void**)&r_z,   g_z_r);
    cudaGetSymbolAddress((void**)&r_W1,  g_W1r);
    cudaGetSymbolAddress((void**)&r_W2,  g_W2r);
    cudaGetSymbolAddress((void**)&r_W3,  g_W3r);
    cudaGetSymbolAddress((void**)&r_W4,  g_W4r);

    float* concat = (float*)d_out;
    const int concat_elems = B_ * T_ * 2 * D_;
    const int attn_elems   = B_ * T_ * D_;
    float* attn_out = (out_size >= concat_elems + attn_elems)
                        ? concat + concat_elems : nullptr;

    cudaFuncSetAttribute(fused_gemm_tf32,
                         cudaFuncAttributeMaxDynamicSharedMemorySize,
                         GEMM_SMEM_BYTES);

    // Pre-round all GEMM inputs to tf32 (rna). Block = 1024 floats.
    PRDs PR;
    PR.p[0] = { enc,    r_enc,    0 };
    PR.p[1] = { output, r_out,  512 };
    PR.p[2] = { z,      r_z,    640 };
    PR.p[3] = { W1,     r_W1,   768 };
    PR.p[4] = { W2,     r_W2,  1024 };
    PR.p[5] = { W3,     r_W3,  1280 };
    PR.p[6] = { W4,     r_W4,  1344 };
    preround_tf32<<<1600, 256>>>(PR);

    // GEMM blocks (heavy first, light lin3 last):
    //  lin1: 16m x 8n = 128 (base 0), lin2: 32 (128), lin4: 32 (160), lin3: 128 (192)
    Descs P;
    P.d[0] = { r_enc, r_W1, b1, p_hs,  E_, 0,   0, D_ / BN };
    P.d[1] = { r_out, r_W2, b2, p_o2,  D_, 1, 128, D_ / BN };
    P.d[2] = { r_out, r_W4, b4, p_o3,  D_, 1, 160, D_ / BN };
    P.d[3] = { r_z,   r_W3, b3, p_fds, F_, 0, 192, D_ / BN };

    fused_gemm_tf32<<<320, 256, GEMM_SMEM_BYTES>>>(P);

    dual_attn_partial<<<dim3(D_ / 128, T_ / TT, B_ * SCH), 128>>>(
        p_hs, p_fds, enc, p_o2, p_o3, p_s1, p_s2);

    attn_finalize<<<dim3(4, T_, B_), 128>>>(
        p_s1, p_s2, output, concat, attn_out);
}